// round 4
// baseline (speedup 1.0000x reference)
#include <cuda_runtime.h>
#include <cuda_bf16.h>
#include <math.h>

#define D 512
#define WARPS_PER_BLOCK 8
#define THREADS (WARPS_PER_BLOCK * 32)
#define MAX_BLOCKS 32768

// Per-block partials, overwritten every launch (no init kernel required).
__device__ float g_pos_part[MAX_BLOCKS];
__device__ float g_neg_part[MAX_BLOCKS];
__device__ float g_cnt_part[MAX_BLOCKS];

// softplus with overflow guard: log1p(exp(x)) = max(x,0) + log1p(exp(-|x|))
__device__ __forceinline__ float softplus_f(float x) {
    return fmaxf(x, 0.0f) + log1pf(__expf(-fabsf(x)));
}

__global__ void __launch_bounds__(THREADS, 8)
bl_main_kernel(const float* __restrict__ o1,
               const float* __restrict__ o2,
               const void* __restrict__ tgt,
               int n) {
    __shared__ float s_pos[WARPS_PER_BLOCK];
    __shared__ float s_neg[WARPS_PER_BLOCK];
    __shared__ int   s_cnt[WARPS_PER_BLOCK];
    __shared__ int   s_is64;

    const int lane = threadIdx.x & 31;
    const int wid  = threadIdx.x >> 5;

    // Dtype probe: int64 little-endian 0/1 targets have every odd 32-bit word
    // zero; int32 targets have ~Bernoulli(0.5) nonzero odd words. All blocks
    // probe the SAME 64 words -> globally consistent, L2-hot after block 0.
    if (wid == 0) {
        const int* tw = (const int*)tgt;
        int v = 0;
        int w0 = 2 * lane + 1;          // words 1..63
        int w1 = 2 * (lane + 32) + 1;   // words 65..127
        if (w0 < n) v |= tw[w0];
        if (w1 < n) v |= tw[w1];
        unsigned any = __ballot_sync(0xffffffffu, v != 0);
        if (lane == 0) s_is64 = (any == 0u) ? 1 : 0;
    }
    __syncthreads();
    const int is64 = s_is64;

    const long long row = (long long)blockIdx.x * WARPS_PER_BLOCK + wid;

    float pos_t = 0.0f, neg_t = 0.0f;
    int   cnt_t = 0;

    if (row < n) {
        const float4* __restrict__ a = (const float4*)(o1 + row * D);
        const float4* __restrict__ b = (const float4*)(o2 + row * D);

        float dot = 0.0f, na = 0.0f, nb = 0.0f;
        #pragma unroll
        for (int i = 0; i < 4; ++i) {
            float4 x = a[lane + i * 32];
            float4 y = b[lane + i * 32];
            dot = fmaf(x.x, y.x, dot); dot = fmaf(x.y, y.y, dot);
            dot = fmaf(x.z, y.z, dot); dot = fmaf(x.w, y.w, dot);
            na  = fmaf(x.x, x.x, na);  na  = fmaf(x.y, x.y, na);
            na  = fmaf(x.z, x.z, na);  na  = fmaf(x.w, x.w, na);
            nb  = fmaf(y.x, y.x, nb);  nb  = fmaf(y.y, y.y, nb);
            nb  = fmaf(y.z, y.z, nb);  nb  = fmaf(y.w, y.w, nb);
        }
        #pragma unroll
        for (int off = 16; off > 0; off >>= 1) {
            dot += __shfl_xor_sync(0xffffffffu, dot, off);
            na  += __shfl_xor_sync(0xffffffffu, na,  off);
            nb  += __shfl_xor_sync(0xffffffffu, nb,  off);
        }

        if (lane == 0) {
            float denom = fmaxf(sqrtf(na) * sqrtf(nb), 1e-6f);
            float d = dot / denom;
            bool is_pos;
            if (is64) {
                is_pos = (((const long long*)tgt)[row] == 1ll);
            } else {
                is_pos = (((const int*)tgt)[row] == 1);
            }
            if (is_pos) {
                // (2/BETA) * softplus(-BETA*(d-0.5)), BETA=0.5
                pos_t = 4.0f * softplus_f(-0.5f * (d - 0.5f));
                cnt_t = 1;
            } else {
                // (2/ALPHA) * softplus(ALPHA*(d-2)), ALPHA=50
                neg_t = 0.04f * softplus_f(50.0f * (d - 2.0f));
            }
        }
    }

    if (lane == 0) {
        s_pos[wid] = pos_t;
        s_neg[wid] = neg_t;
        s_cnt[wid] = cnt_t;
    }
    __syncthreads();

    if (threadIdx.x == 0) {
        float bp = 0.0f, bn = 0.0f;
        int bc = 0;
        #pragma unroll
        for (int w = 0; w < WARPS_PER_BLOCK; ++w) {
            bp += s_pos[w];
            bn += s_neg[w];
            bc += s_cnt[w];
        }
        g_pos_part[blockIdx.x] = bp;
        g_neg_part[blockIdx.x] = bn;
        g_cnt_part[blockIdx.x] = (float)bc;  // <= 8, exact in float
    }
}

#define FIN_THREADS 512

__global__ void bl_finalize_kernel(float* __restrict__ out, int n, int nblocks) {
    __shared__ double sp[FIN_THREADS / 32];
    __shared__ double sn[FIN_THREADS / 32];
    __shared__ double sc[FIN_THREADS / 32];

    const int tid  = threadIdx.x;
    const int lane = tid & 31;
    const int wid  = tid >> 5;

    double p = 0.0, q = 0.0, c = 0.0;
    for (int i = tid; i < nblocks; i += FIN_THREADS) {
        p += (double)g_pos_part[i];
        q += (double)g_neg_part[i];
        c += (double)g_cnt_part[i];
    }
    #pragma unroll
    for (int off = 16; off > 0; off >>= 1) {
        p += __shfl_xor_sync(0xffffffffu, p, off);
        q += __shfl_xor_sync(0xffffffffu, q, off);
        c += __shfl_xor_sync(0xffffffffu, c, off);
    }
    if (lane == 0) { sp[wid] = p; sn[wid] = q; sc[wid] = c; }
    __syncthreads();

    if (tid == 0) {
        double tp = 0.0, tn = 0.0, tc = 0.0;
        #pragma unroll
        for (int w = 0; w < FIN_THREADS / 32; ++w) {
            tp += sp[w]; tn += sn[w]; tc += sc[w];
        }
        double np = tc;
        double nn = (double)n - np;
        double pl = tp / fmax(np, 1.0);
        double nl = tn / fmax(nn, 1.0);
        out[0] = (float)(pl + nl);
    }
}

extern "C" void kernel_launch(void* const* d_in, const int* in_sizes, int n_in,
                              void* d_out, int out_size) {
    const float* o1  = (const float*)d_in[0];
    const float* o2  = (const float*)d_in[1];
    const void*  tgt = d_in[2];
    const int n = in_sizes[2];  // number of rows (target element count)

    int blocks = (n + WARPS_PER_BLOCK - 1) / WARPS_PER_BLOCK;
    if (blocks > MAX_BLOCKS) blocks = MAX_BLOCKS;  // n <= 262144 expected

    bl_main_kernel<<<blocks, THREADS>>>(o1, o2, tgt, n);
    bl_finalize_kernel<<<1, FIN_THREADS>>>((float*)d_out, n, blocks);
}

// round 5
// speedup vs baseline: 1.4034x; 1.4034x over previous
#include <cuda_runtime.h>
#include <cuda_bf16.h>
#include <math.h>

#define D 512
#define WARPS_PER_BLOCK 8
#define THREADS (WARPS_PER_BLOCK * 32)

// Zero-initialized at module load; finalize kernel re-zeroes them after each
// launch, so every (graph-replayed) launch sees clean accumulators.
__device__ double g_pos_sum;
__device__ double g_neg_sum;
__device__ unsigned long long g_num_pos;

// softplus with overflow guard: log1p(exp(x)) = max(x,0) + log1p(exp(-|x|))
__device__ __forceinline__ float softplus_f(float x) {
    return fmaxf(x, 0.0f) + log1pf(__expf(-fabsf(x)));
}

__global__ void __launch_bounds__(THREADS, 8)
bl_main_kernel(const float* __restrict__ o1,
               const float* __restrict__ o2,
               const void* __restrict__ tgt,
               int n) {
    __shared__ float s_pos[WARPS_PER_BLOCK];
    __shared__ float s_neg[WARPS_PER_BLOCK];
    __shared__ int   s_cnt[WARPS_PER_BLOCK];
    __shared__ int   s_is64;

    const int lane = threadIdx.x & 31;
    const int wid  = threadIdx.x >> 5;

    // Dtype probe: int64 little-endian 0/1 targets have every odd 32-bit word
    // zero; int32 targets have ~Bernoulli(0.5) nonzero odd words. All blocks
    // probe the SAME 64 words -> globally consistent, L2-hot after block 0.
    if (wid == 0) {
        const int* tw = (const int*)tgt;
        int v = 0;
        int w0 = 2 * lane + 1;          // words 1..63
        int w1 = 2 * (lane + 32) + 1;   // words 65..127
        if (w0 < n) v |= tw[w0];
        if (w1 < n) v |= tw[w1];
        unsigned any = __ballot_sync(0xffffffffu, v != 0);
        if (lane == 0) s_is64 = (any == 0u) ? 1 : 0;
    }
    __syncthreads();
    const int is64 = s_is64;

    const long long row = (long long)blockIdx.x * WARPS_PER_BLOCK + wid;

    float pos_t = 0.0f, neg_t = 0.0f;
    int   cnt_t = 0;

    if (row < n) {
        const float4* __restrict__ a = (const float4*)(o1 + row * D);
        const float4* __restrict__ b = (const float4*)(o2 + row * D);

        float dot = 0.0f, na = 0.0f, nb = 0.0f;
        #pragma unroll
        for (int i = 0; i < 4; ++i) {
            float4 x = a[lane + i * 32];
            float4 y = b[lane + i * 32];
            dot = fmaf(x.x, y.x, dot); dot = fmaf(x.y, y.y, dot);
            dot = fmaf(x.z, y.z, dot); dot = fmaf(x.w, y.w, dot);
            na  = fmaf(x.x, x.x, na);  na  = fmaf(x.y, x.y, na);
            na  = fmaf(x.z, x.z, na);  na  = fmaf(x.w, x.w, na);
            nb  = fmaf(y.x, y.x, nb);  nb  = fmaf(y.y, y.y, nb);
            nb  = fmaf(y.z, y.z, nb);  nb  = fmaf(y.w, y.w, nb);
        }
        #pragma unroll
        for (int off = 16; off > 0; off >>= 1) {
            dot += __shfl_xor_sync(0xffffffffu, dot, off);
            na  += __shfl_xor_sync(0xffffffffu, na,  off);
            nb  += __shfl_xor_sync(0xffffffffu, nb,  off);
        }

        if (lane == 0) {
            float denom = fmaxf(sqrtf(na) * sqrtf(nb), 1e-6f);
            float d = dot / denom;
            bool is_pos;
            if (is64) {
                is_pos = (((const long long*)tgt)[row] == 1ll);
            } else {
                is_pos = (((const int*)tgt)[row] == 1);
            }
            if (is_pos) {
                // (2/BETA) * softplus(-BETA*(d-0.5)), BETA=0.5
                pos_t = 4.0f * softplus_f(-0.5f * (d - 0.5f));
                cnt_t = 1;
            } else {
                // (2/ALPHA) * softplus(ALPHA*(d-2)), ALPHA=50
                neg_t = 0.04f * softplus_f(50.0f * (d - 2.0f));
            }
        }
    }

    if (lane == 0) {
        s_pos[wid] = pos_t;
        s_neg[wid] = neg_t;
        s_cnt[wid] = cnt_t;
    }
    __syncthreads();

    if (threadIdx.x == 0) {
        float bp = 0.0f, bn = 0.0f;
        int bc = 0;
        #pragma unroll
        for (int w = 0; w < WARPS_PER_BLOCK; ++w) {
            bp += s_pos[w];
            bn += s_neg[w];
            bc += s_cnt[w];
        }
        if (bp != 0.0f) atomicAdd(&g_pos_sum, (double)bp);
        if (bn != 0.0f) atomicAdd(&g_neg_sum, (double)bn);
        if (bc != 0)    atomicAdd(&g_num_pos, (unsigned long long)bc);
    }
}

__global__ void bl_finalize_kernel(float* __restrict__ out, int n) {
    if (threadIdx.x == 0 && blockIdx.x == 0) {
        double np = (double)g_num_pos;
        double nn = (double)n - np;
        double pl = g_pos_sum / fmax(np, 1.0);
        double nl = g_neg_sum / fmax(nn, 1.0);
        out[0] = (float)(pl + nl);
        // Reset for the next launch (graph replay): leaves state identical to
        // the module-load state, keeping every launch deterministic.
        g_pos_sum = 0.0;
        g_neg_sum = 0.0;
        g_num_pos = 0ull;
    }
}

extern "C" void kernel_launch(void* const* d_in, const int* in_sizes, int n_in,
                              void* d_out, int out_size) {
    const float* o1  = (const float*)d_in[0];
    const float* o2  = (const float*)d_in[1];
    const void*  tgt = d_in[2];
    const int n = in_sizes[2];  // number of rows (target element count)

    const int blocks = (n + WARPS_PER_BLOCK - 1) / WARPS_PER_BLOCK;
    bl_main_kernel<<<blocks, THREADS>>>(o1, o2, tgt, n);
    bl_finalize_kernel<<<1, 32>>>((float*)d_out, n);
}